// round 5
// baseline (speedup 1.0000x reference)
#include <cuda_runtime.h>
#include <cstdint>
#include <cmath>

#define N_KERNELS 2000
#define K_MAX     11
#define SIG_LEN   32768
#define MAX_GROUPS 128
#define THREADS   256
#define TILE      (THREADS * 4)
#define WIN       (TILE + (K_MAX - 1) * 2 + 8)   // smem window for d<=2 (1052 floats)

// ---------------------------------------------------------------------------
// Parameters passed by value (kernel param space; graph-capture safe)
// ---------------------------------------------------------------------------
struct Params {
    int  idx[N_KERNELS];        // group-ordered -> original kernel index
    int4 gA[MAX_GROUPS];        // {d, p, Lout, G}  (reference (k,d,p) order)
    int4 gB[MAX_GROUPS];        // {idx_base, out_off, kcode(0/1/2), mode(0/1)}
    int  tprefix[MAX_GROUPS+1]; // cumulative tile counts
    int  ng;
};

// ---- packed f32x2 helpers (sm_103a FFMA2 is PTX-only) ----------------------
__device__ __forceinline__ unsigned long long pk(float lo, float hi) {
    unsigned long long r;
    asm("mov.b64 %0, {%1, %2};" : "=l"(r) : "f"(lo), "f"(hi));
    return r;
}
__device__ __forceinline__ unsigned long long fma2(unsigned long long a,
                                                   unsigned long long b,
                                                   unsigned long long c) {
    unsigned long long r;
    asm("fma.rn.f32x2 %0, %1, %2, %3;" : "=l"(r) : "l"(a), "l"(b), "l"(c));
    return r;
}
__device__ __forceinline__ void st2s(float* p, unsigned long long v) {
    float lo, hi;
    asm("mov.b64 {%0, %1}, %2;" : "=f"(lo), "=f"(hi) : "l"(v));
    __stcs(reinterpret_cast<float2*>(p), make_float2(lo, hi));
}

// ---------------------------------------------------------------------------
// Templated work body. MODE 0: d>=4 (d%4==0, p%4==0) -> aligned LDG.128 / tap.
// MODE 1: d<=2 -> stage block window into smem, LDS per tap.
// Thread owns 4 consecutive positions (2 packed f32x2 accumulators); inner
// loop processes TWO kernels per iteration (4 independent FMA chains) and
// reads weights via LDS.128 (ulonglong2: pairs (w0,w1)..(w_{K-1},bias)).
// ---------------------------------------------------------------------------
template<int K, int MODE>
__device__ __forceinline__ void body(const Params& prm,
                                     int d, int p, int Lout, int G,
                                     int idx_base, int out_off,
                                     int t0, int s,
                                     const float* __restrict__ sig,
                                     const float* __restrict__ W,
                                     const float* __restrict__ B,
                                     float* __restrict__ out,
                                     char* smem)
{
    constexpr int ROW = K + 1;          // u64 per kernel row (even for odd K)
    constexpr int HP  = ROW / 2;        // ulonglong2 per row

    float* sws = reinterpret_cast<float*>(smem);                 // WIN floats
    unsigned long long* smw =
        reinterpret_cast<unsigned long long*>(smem + WIN * sizeof(float));

    // Stage duplicated weight pairs {w,w} and bias pair {b,b}
    for (int j = threadIdx.x; j < G * ROW; j += THREADS) {
        const int jj = j / ROW, q = j - jj * ROW;
        const int orig = prm.idx[idx_base + jj];
        const float v = (q < K) ? W[orig * K_MAX + q] : B[orig];
        smw[j] = pk(v, v);
    }

    const float* __restrict__ x = sig + s * SIG_LEN;
    const int t = t0 + threadIdx.x * 4;
    const int base = t - p;

    unsigned long long xi[K][2];

    if (MODE == 1) {
        const int wbase = t0 - p;
        for (int i = threadIdx.x; i < WIN; i += THREADS) {
            const int pos = wbase + i;
            sws[i] = ((unsigned)pos < (unsigned)SIG_LEN) ? x[pos] : 0.0f;
        }
        __syncthreads();
        const int o0 = threadIdx.x * 4;
#pragma unroll
        for (int q = 0; q < K; q++) {
            const int o = o0 + q * d;
            xi[q][0] = pk(sws[o],     sws[o + 1]);
            xi[q][1] = pk(sws[o + 2], sws[o + 3]);
        }
    } else {
        __syncthreads();
        if (base >= 0 && base + 3 + (K - 1) * d < SIG_LEN) {
#pragma unroll
            for (int q = 0; q < K; q++) {
                const float4 v = __ldg(reinterpret_cast<const float4*>(x + base + q * d));
                xi[q][0] = pk(v.x, v.y);
                xi[q][1] = pk(v.z, v.w);
            }
        } else {
#pragma unroll
            for (int q = 0; q < K; q++) {
                float v[4];
#pragma unroll
                for (int ii = 0; ii < 4; ii++) {
                    const int pos = base + ii + q * d;
                    v[ii] = ((unsigned)pos < (unsigned)SIG_LEN) ? __ldg(x + pos) : 0.0f;
                }
                xi[q][0] = pk(v[0], v[1]);
                xi[q][1] = pk(v[2], v[3]);
            }
        }
    }

    const bool full = (t0 + TILE <= Lout);
    const bool ok0 = (t < Lout);
    const bool ok1 = (t + 2 < Lout);
    float* orow = out + (size_t)out_off + (size_t)(s * G) * (size_t)Lout + t;
    const ulonglong2* wv = reinterpret_cast<const ulonglong2*>(smw);

    int j = 0;
    for (; j + 2 <= G; j += 2) {
        const ulonglong2* wr0 = wv + (size_t)j * HP;
        const ulonglong2* wr1 = wr0 + HP;

        // last pair of each row is {w_{K-1}, bias}
        ulonglong2 lp0 = wr0[HP - 1];
        ulonglong2 lp1 = wr1[HP - 1];
        unsigned long long a00 = lp0.y, a01 = lp0.y;   // j   : bias
        unsigned long long a10 = lp1.y, a11 = lp1.y;   // j+1 : bias
        a00 = fma2(lp0.x, xi[K - 1][0], a00);
        a01 = fma2(lp0.x, xi[K - 1][1], a01);
        a10 = fma2(lp1.x, xi[K - 1][0], a10);
        a11 = fma2(lp1.x, xi[K - 1][1], a11);
#pragma unroll
        for (int h = 0; h < HP - 1; h++) {
            const ulonglong2 w0 = wr0[h];
            const ulonglong2 w1 = wr1[h];
            a00 = fma2(w0.x, xi[2 * h][0], a00);
            a01 = fma2(w0.x, xi[2 * h][1], a01);
            a10 = fma2(w1.x, xi[2 * h][0], a10);
            a11 = fma2(w1.x, xi[2 * h][1], a11);
            a00 = fma2(w0.y, xi[2 * h + 1][0], a00);
            a01 = fma2(w0.y, xi[2 * h + 1][1], a01);
            a10 = fma2(w1.y, xi[2 * h + 1][0], a10);
            a11 = fma2(w1.y, xi[2 * h + 1][1], a11);
        }
        if (full) {
            st2s(orow, a00);            st2s(orow + 2, a01);
            st2s(orow + Lout, a10);     st2s(orow + Lout + 2, a11);
        } else {
            if (ok0) { st2s(orow, a00);      st2s(orow + Lout, a10); }
            if (ok1) { st2s(orow + 2, a01);  st2s(orow + Lout + 2, a11); }
        }
        orow += 2 * Lout;
    }
    if (j < G) {
        const ulonglong2* wr0 = wv + (size_t)j * HP;
        ulonglong2 lp0 = wr0[HP - 1];
        unsigned long long a00 = lp0.y, a01 = lp0.y;
        a00 = fma2(lp0.x, xi[K - 1][0], a00);
        a01 = fma2(lp0.x, xi[K - 1][1], a01);
#pragma unroll
        for (int h = 0; h < HP - 1; h++) {
            const ulonglong2 w0 = wr0[h];
            a00 = fma2(w0.x, xi[2 * h][0], a00);
            a01 = fma2(w0.x, xi[2 * h][1], a01);
            a00 = fma2(w0.y, xi[2 * h + 1][0], a00);
            a01 = fma2(w0.y, xi[2 * h + 1][1], a01);
        }
        if (full) {
            st2s(orow, a00); st2s(orow + 2, a01);
        } else {
            if (ok0) st2s(orow, a00);
            if (ok1) st2s(orow + 2, a01);
        }
    }
}

// ---------------------------------------------------------------------------
// Single fat kernel: block = one (group, tile) pair x sample. Exact mapping
// via per-group tile prefix (binary search, uniform per block).
// ---------------------------------------------------------------------------
__global__ void __launch_bounds__(THREADS, 3)
rocket_all(const __grid_constant__ Params prm,
           const float* __restrict__ sig,
           const float* __restrict__ W,
           const float* __restrict__ B,
           float* __restrict__ out)
{
    extern __shared__ char smem[];
    const int bid = blockIdx.x;
    int lo = 0, hi = prm.ng - 1;
    while (lo < hi) {
        const int mid = (lo + hi + 1) >> 1;
        if (prm.tprefix[mid] <= bid) lo = mid; else hi = mid - 1;
    }
    const int g = lo;
    const int t0 = (bid - prm.tprefix[g]) * TILE;
    const int s = blockIdx.y;

    const int4 ga = prm.gA[g];
    const int4 gb = prm.gB[g];
    const int code = gb.z * 2 + gb.w;     // kcode*2 + mode

    switch (code) {
    case 0: body<7, 0>(prm, ga.x, ga.y, ga.z, ga.w, gb.x, gb.y, t0, s, sig, W, B, out, smem); break;
    case 1: body<7, 1>(prm, ga.x, ga.y, ga.z, ga.w, gb.x, gb.y, t0, s, sig, W, B, out, smem); break;
    case 2: body<9, 0>(prm, ga.x, ga.y, ga.z, ga.w, gb.x, gb.y, t0, s, sig, W, B, out, smem); break;
    case 3: body<9, 1>(prm, ga.x, ga.y, ga.z, ga.w, gb.x, gb.y, t0, s, sig, W, B, out, smem); break;
    case 4: body<11,0>(prm, ga.x, ga.y, ga.z, ga.w, gb.x, gb.y, t0, s, sig, W, B, out, smem); break;
    case 5: body<11,1>(prm, ga.x, ga.y, ga.z, ga.w, gb.x, gb.y, t0, s, sig, W, B, out, smem); break;
    }
}

// ---------------------------------------------------------------------------
// Host-side bit-exact replication of numpy.random.RandomState(0) meta stream
// ---------------------------------------------------------------------------
namespace mtrep {

struct MT {
    uint32_t mt[624];
    int mti;
    bool has_gauss;
    double gauss_cache;

    void seed(uint32_t s) {
        mt[0] = s;
        for (int i = 1; i < 624; i++)
            mt[i] = 1812433253u * (mt[i - 1] ^ (mt[i - 1] >> 30)) + (uint32_t)i;
        mti = 624;
        has_gauss = false;
        gauss_cache = 0.0;
    }
    uint32_t next() {
        if (mti >= 624) {
            for (int i = 0; i < 624; i++) {
                uint32_t y = (mt[i] & 0x80000000u) | (mt[(i + 1) % 624] & 0x7fffffffu);
                mt[i] = mt[(i + 397) % 624] ^ (y >> 1) ^ ((y & 1u) ? 0x9908b0dfu : 0u);
            }
            mti = 0;
        }
        uint32_t y = mt[mti++];
        y ^= y >> 11;
        y ^= (y << 7) & 0x9d2c5680u;
        y ^= (y << 15) & 0xefc60000u;
        y ^= y >> 18;
        return y;
    }
    double rd() {
        uint32_t a = next() >> 5, b = next() >> 6;
        return (a * 67108864.0 + b) / 9007199254740992.0;
    }
    uint32_t masked(uint32_t rngmax, uint32_t mask) {
        for (;;) {
            uint32_t v = next() & mask;
            if (v <= rngmax) return v;
        }
    }
    double gauss() {
        if (has_gauss) { has_gauss = false; return gauss_cache; }
        double x1, x2, r2;
        do {
            x1 = 2.0 * rd() - 1.0;
            x2 = 2.0 * rd() - 1.0;
            r2 = x1 * x1 + x2 * x2;
        } while (r2 >= 1.0 || r2 == 0.0);
        double f = sqrt(-2.0 * log(r2) / r2);
        gauss_cache = f * x1;
        has_gauss = true;
        return f * x2;
    }
};

} // namespace mtrep

extern "C" void kernel_launch(void* const* d_in, const int* in_sizes, int n_in,
                              void* d_out, int out_size)
{
    (void)in_sizes; (void)n_in; (void)out_size;
    const float* sig = (const float*)d_in[0];
    const float* W   = (const float*)d_in[1];
    const float* B   = (const float*)d_in[2];
    float* out       = (float*)d_out;

    // ---- replicate gen_meta() ----
    static int kk[N_KERNELS], dd[N_KERNELS], pp[N_KERNELS];
    {
        mtrep::MT r;
        r.seed(0u);
        for (int i = 0; i < N_KERNELS; i++) {
            uint32_t c = r.masked(2u, 3u);               // choice of 3
            int k = (c == 0u) ? 7 : (c == 1u) ? 9 : 11;
            int emax = (k == 7) ? 12 : 11;               // int(log2((L-1)/(k-1)))
            uint32_t e = r.masked((uint32_t)(emax - 1), 15u);
            int d = 1 << e;
            double rv = r.rd();                          // rng.rand()
            int p = (rv <= 0.5) ? 0 : ((k - 1) * d / 2);
            (void)r.rd();                                // rng.uniform(-1,1) bias
            for (int q = 0; q < k; q++) (void)r.gauss(); // normal(size=k)
            kk[i] = k; dd[i] = d; pp[i] = p;
        }
    }

    // ---- group by (k,d,p), sort groups lexicographically (reference order) --
    static int gk[MAX_GROUPS], gd[MAX_GROUPS], gp[MAX_GROUPS], gcnt[MAX_GROUPS];
    static int gid_of[N_KERNELS];
    int ng = 0;
    for (int i = 0; i < N_KERNELS; i++) {
        int found = -1;
        for (int g = 0; g < ng; g++)
            if (gk[g] == kk[i] && gd[g] == dd[i] && gp[g] == pp[i]) { found = g; break; }
        if (found < 0) {
            found = ng++;
            gk[found] = kk[i]; gd[found] = dd[i]; gp[found] = pp[i]; gcnt[found] = 0;
        }
        gid_of[i] = found;
        gcnt[found]++;
    }
    static int order[MAX_GROUPS];
    for (int g = 0; g < ng; g++) order[g] = g;
    for (int a = 0; a < ng; a++) {                       // selection sort by (k,d,p)
        int best = a;
        for (int b = a + 1; b < ng; b++) {
            int ga_ = order[best], gb_ = order[b];
            bool lt = (gk[gb_] < gk[ga_]) ||
                      (gk[gb_] == gk[ga_] && (gd[gb_] < gd[ga_] ||
                       (gd[gb_] == gd[ga_] && gp[gb_] < gp[ga_])));
            if (lt) best = b;
        }
        int tmp = order[a]; order[a] = order[best]; order[best] = tmp;
    }

    // ---- build params in reference order (out offsets fixed by (k,d,p)) ----
    static Params prm;
    int pos = 0;
    long long off = 0;
    int tiles = 0, maxG = 1;
    for (int si = 0; si < ng; si++) {
        int g = order[si];
        int G = gcnt[g];
        int Lout = SIG_LEN + 2 * gp[g] - (gk[g] - 1) * gd[g];
        const int kcode = (gk[g] == 7) ? 0 : (gk[g] == 9) ? 1 : 2;
        const int mode = (gd[g] >= 4) ? 0 : 1;
        prm.gA[si] = make_int4(gd[g], gp[g], Lout, G);
        prm.gB[si] = make_int4(pos, (int)off, kcode, mode);
        prm.tprefix[si] = tiles;
        tiles += (Lout + TILE - 1) / TILE;
        for (int i = 0; i < N_KERNELS; i++)
            if (gid_of[i] == g) prm.idx[pos++] = i;
        off += 2LL * G * Lout;
        if (G > maxG) maxG = G;
    }
    prm.tprefix[ng] = tiles;
    prm.ng = ng;

    // ---- single launch ----
    dim3 grid(tiles, 2);
    const int smem = WIN * (int)sizeof(float)
                   + maxG * (K_MAX + 1) * (int)sizeof(unsigned long long);
    rocket_all<<<grid, THREADS, smem>>>(prm, sig, W, B, out);
}

// round 6
// speedup vs baseline: 1.1417x; 1.1417x over previous
#include <cuda_runtime.h>
#include <cstdint>
#include <cmath>

#define N_KERNELS 2000
#define K_MAX     11
#define SIG_LEN   32768
#define MAX_GROUPS 128
#define THREADS   256
#define TILE      (THREADS * 4)
#define WIN       (TILE + (K_MAX - 1) * 2 + 8)   // smem window for d<=2 (1052 floats)

// ---------------------------------------------------------------------------
// Parameters passed by value (kernel param space; graph-capture safe)
// ---------------------------------------------------------------------------
struct Params {
    int  idx[N_KERNELS];        // group-ordered -> original kernel index
    int4 gA[MAX_GROUPS];        // {d, p, Lout, G}  (reference (k,d,p) order)
    int4 gB[MAX_GROUPS];        // {idx_base, out_off, code, unused}
    int  tprefix[MAX_GROUPS+1]; // cumulative tile counts
    int  ng;
};

// ---- packed f32x2 helpers (sm_103a FFMA2 is PTX-only) ----------------------
__device__ __forceinline__ unsigned long long pk(float lo, float hi) {
    unsigned long long r;
    asm("mov.b64 %0, {%1, %2};" : "=l"(r) : "f"(lo), "f"(hi));
    return r;
}
__device__ __forceinline__ unsigned long long fma2(unsigned long long a,
                                                   unsigned long long b,
                                                   unsigned long long c) {
    unsigned long long r;
    asm("fma.rn.f32x2 %0, %1, %2, %3;" : "=l"(r) : "l"(a), "l"(b), "l"(c));
    return r;
}
__device__ __forceinline__ void st2s(float* p, unsigned long long v) {
    float lo, hi;
    asm("mov.b64 {%0, %1}, %2;" : "=f"(lo), "=f"(hi) : "l"(v));
    __stcs(reinterpret_cast<float2*>(p), make_float2(lo, hi));
}
// dense 16B streaming store of two packed accumulators (4 consecutive floats)
__device__ __forceinline__ void st4s(float* p, unsigned long long a,
                                     unsigned long long b) {
    float x, y, z, w;
    asm("mov.b64 {%0, %1}, %2;" : "=f"(x), "=f"(y) : "l"(a));
    asm("mov.b64 {%0, %1}, %2;" : "=f"(z), "=f"(w) : "l"(b));
    __stcs(reinterpret_cast<float4*>(p), make_float4(x, y, z, w));
}

// ---------------------------------------------------------------------------
// Templated work body. MODE 0: d>=4 (d%4==0, p%4==0) -> aligned LDG.128 / tap.
// MODE 1: d<=2 -> stage block window into smem, LDS per tap.
// AL: Lout % 4 == 0 -> every output row base is 16B-aligned -> STG.128.
// Thread owns 4 consecutive positions (2 packed f32x2 accumulators); inner
// loop processes TWO kernels per iteration; weights read via LDS.128.
// ---------------------------------------------------------------------------
template<int K, int MODE, bool AL>
__device__ __forceinline__ void body(const Params& prm,
                                     int d, int p, int Lout, int G,
                                     int idx_base, int out_off,
                                     int t0, int s,
                                     const float* __restrict__ sig,
                                     const float* __restrict__ W,
                                     const float* __restrict__ B,
                                     float* __restrict__ out,
                                     char* smem)
{
    constexpr int ROW = K + 1;          // u64 per kernel row (even for odd K)
    constexpr int HP  = ROW / 2;        // ulonglong2 per row

    float* sws = reinterpret_cast<float*>(smem);                 // WIN floats
    unsigned long long* smw =
        reinterpret_cast<unsigned long long*>(smem + WIN * sizeof(float));

    // Stage duplicated weight pairs {w,w} and bias pair {b,b}
    for (int j = threadIdx.x; j < G * ROW; j += THREADS) {
        const int jj = j / ROW, q = j - jj * ROW;
        const int orig = prm.idx[idx_base + jj];
        const float v = (q < K) ? W[orig * K_MAX + q] : B[orig];
        smw[j] = pk(v, v);
    }

    const float* __restrict__ x = sig + s * SIG_LEN;
    const int t = t0 + threadIdx.x * 4;
    const int base = t - p;

    unsigned long long xi[K][2];

    if (MODE == 1) {
        const int wbase = t0 - p;
        for (int i = threadIdx.x; i < WIN; i += THREADS) {
            const int pos = wbase + i;
            sws[i] = ((unsigned)pos < (unsigned)SIG_LEN) ? x[pos] : 0.0f;
        }
        __syncthreads();
        const int o0 = threadIdx.x * 4;
#pragma unroll
        for (int q = 0; q < K; q++) {
            const int o = o0 + q * d;
            xi[q][0] = pk(sws[o],     sws[o + 1]);
            xi[q][1] = pk(sws[o + 2], sws[o + 3]);
        }
    } else {
        __syncthreads();
        if (base >= 0 && base + 3 + (K - 1) * d < SIG_LEN) {
#pragma unroll
            for (int q = 0; q < K; q++) {
                const float4 v = __ldg(reinterpret_cast<const float4*>(x + base + q * d));
                xi[q][0] = pk(v.x, v.y);
                xi[q][1] = pk(v.z, v.w);
            }
        } else {
#pragma unroll
            for (int q = 0; q < K; q++) {
                float v[4];
#pragma unroll
                for (int ii = 0; ii < 4; ii++) {
                    const int pos = base + ii + q * d;
                    v[ii] = ((unsigned)pos < (unsigned)SIG_LEN) ? __ldg(x + pos) : 0.0f;
                }
                xi[q][0] = pk(v[0], v[1]);
                xi[q][1] = pk(v[2], v[3]);
            }
        }
    }

    const bool full = (t0 + TILE <= Lout);
    const bool ok0 = (t < Lout);        // AL: t%4==0 & Lout%4==0 -> whole float4 in range
    const bool ok1 = (t + 2 < Lout);
    float* orow = out + (size_t)out_off + (size_t)(s * G) * (size_t)Lout + t;
    const ulonglong2* wv = reinterpret_cast<const ulonglong2*>(smw);

    int j = 0;
    for (; j + 2 <= G; j += 2) {
        const ulonglong2* wr0 = wv + (size_t)j * HP;
        const ulonglong2* wr1 = wr0 + HP;

        // last pair of each row is {w_{K-1}, bias}
        ulonglong2 lp0 = wr0[HP - 1];
        ulonglong2 lp1 = wr1[HP - 1];
        unsigned long long a00 = lp0.y, a01 = lp0.y;   // j   : bias
        unsigned long long a10 = lp1.y, a11 = lp1.y;   // j+1 : bias
        a00 = fma2(lp0.x, xi[K - 1][0], a00);
        a01 = fma2(lp0.x, xi[K - 1][1], a01);
        a10 = fma2(lp1.x, xi[K - 1][0], a10);
        a11 = fma2(lp1.x, xi[K - 1][1], a11);
#pragma unroll
        for (int h = 0; h < HP - 1; h++) {
            const ulonglong2 w0 = wr0[h];
            const ulonglong2 w1 = wr1[h];
            a00 = fma2(w0.x, xi[2 * h][0], a00);
            a01 = fma2(w0.x, xi[2 * h][1], a01);
            a10 = fma2(w1.x, xi[2 * h][0], a10);
            a11 = fma2(w1.x, xi[2 * h][1], a11);
            a00 = fma2(w0.y, xi[2 * h + 1][0], a00);
            a01 = fma2(w0.y, xi[2 * h + 1][1], a01);
            a10 = fma2(w1.y, xi[2 * h + 1][0], a10);
            a11 = fma2(w1.y, xi[2 * h + 1][1], a11);
        }
        if (AL) {
            if (full) {
                st4s(orow, a00, a01);
                st4s(orow + Lout, a10, a11);
            } else if (ok0) {
                st4s(orow, a00, a01);
                st4s(orow + Lout, a10, a11);
            }
        } else {
            if (full) {
                st2s(orow, a00);            st2s(orow + 2, a01);
                st2s(orow + Lout, a10);     st2s(orow + Lout + 2, a11);
            } else {
                if (ok0) { st2s(orow, a00);      st2s(orow + Lout, a10); }
                if (ok1) { st2s(orow + 2, a01);  st2s(orow + Lout + 2, a11); }
            }
        }
        orow += 2 * Lout;
    }
    if (j < G) {
        const ulonglong2* wr0 = wv + (size_t)j * HP;
        ulonglong2 lp0 = wr0[HP - 1];
        unsigned long long a00 = lp0.y, a01 = lp0.y;
        a00 = fma2(lp0.x, xi[K - 1][0], a00);
        a01 = fma2(lp0.x, xi[K - 1][1], a01);
#pragma unroll
        for (int h = 0; h < HP - 1; h++) {
            const ulonglong2 w0 = wr0[h];
            a00 = fma2(w0.x, xi[2 * h][0], a00);
            a01 = fma2(w0.x, xi[2 * h][1], a01);
            a00 = fma2(w0.y, xi[2 * h + 1][0], a00);
            a01 = fma2(w0.y, xi[2 * h + 1][1], a01);
        }
        if (AL) {
            if (full || ok0) st4s(orow, a00, a01);
        } else {
            if (full) {
                st2s(orow, a00); st2s(orow + 2, a01);
            } else {
                if (ok0) st2s(orow, a00);
                if (ok1) st2s(orow + 2, a01);
            }
        }
    }
}

// ---------------------------------------------------------------------------
// Single fat kernel: block = one (group, tile) pair x sample. Exact mapping
// via per-group tile prefix (binary search, uniform per block).
// ---------------------------------------------------------------------------
__global__ void __launch_bounds__(THREADS, 3)
rocket_all(const __grid_constant__ Params prm,
           const float* __restrict__ sig,
           const float* __restrict__ W,
           const float* __restrict__ B,
           float* __restrict__ out)
{
    extern __shared__ char smem[];
    const int bid = blockIdx.x;
    int lo = 0, hi = prm.ng - 1;
    while (lo < hi) {
        const int mid = (lo + hi + 1) >> 1;
        if (prm.tprefix[mid] <= bid) lo = mid; else hi = mid - 1;
    }
    const int g = lo;
    const int t0 = (bid - prm.tprefix[g]) * TILE;
    const int s = blockIdx.y;

    const int4 ga = prm.gA[g];
    const int4 gb = prm.gB[g];
    const int code = gb.z;     // kcode*4 + mode*2 + aligned

    switch (code) {
    case 0:  body<7, 0,false>(prm, ga.x, ga.y, ga.z, ga.w, gb.x, gb.y, t0, s, sig, W, B, out, smem); break;
    case 1:  body<7, 0,true >(prm, ga.x, ga.y, ga.z, ga.w, gb.x, gb.y, t0, s, sig, W, B, out, smem); break;
    case 2:  body<7, 1,false>(prm, ga.x, ga.y, ga.z, ga.w, gb.x, gb.y, t0, s, sig, W, B, out, smem); break;
    case 3:  body<7, 1,true >(prm, ga.x, ga.y, ga.z, ga.w, gb.x, gb.y, t0, s, sig, W, B, out, smem); break;
    case 4:  body<9, 0,false>(prm, ga.x, ga.y, ga.z, ga.w, gb.x, gb.y, t0, s, sig, W, B, out, smem); break;
    case 5:  body<9, 0,true >(prm, ga.x, ga.y, ga.z, ga.w, gb.x, gb.y, t0, s, sig, W, B, out, smem); break;
    case 6:  body<9, 1,false>(prm, ga.x, ga.y, ga.z, ga.w, gb.x, gb.y, t0, s, sig, W, B, out, smem); break;
    case 7:  body<9, 1,true >(prm, ga.x, ga.y, ga.z, ga.w, gb.x, gb.y, t0, s, sig, W, B, out, smem); break;
    case 8:  body<11,0,false>(prm, ga.x, ga.y, ga.z, ga.w, gb.x, gb.y, t0, s, sig, W, B, out, smem); break;
    case 9:  body<11,0,true >(prm, ga.x, ga.y, ga.z, ga.w, gb.x, gb.y, t0, s, sig, W, B, out, smem); break;
    case 10: body<11,1,false>(prm, ga.x, ga.y, ga.z, ga.w, gb.x, gb.y, t0, s, sig, W, B, out, smem); break;
    case 11: body<11,1,true >(prm, ga.x, ga.y, ga.z, ga.w, gb.x, gb.y, t0, s, sig, W, B, out, smem); break;
    }
}

// ---------------------------------------------------------------------------
// Host-side bit-exact replication of numpy.random.RandomState(0) meta stream
// ---------------------------------------------------------------------------
namespace mtrep {

struct MT {
    uint32_t mt[624];
    int mti;
    bool has_gauss;
    double gauss_cache;

    void seed(uint32_t s) {
        mt[0] = s;
        for (int i = 1; i < 624; i++)
            mt[i] = 1812433253u * (mt[i - 1] ^ (mt[i - 1] >> 30)) + (uint32_t)i;
        mti = 624;
        has_gauss = false;
        gauss_cache = 0.0;
    }
    uint32_t next() {
        if (mti >= 624) {
            for (int i = 0; i < 624; i++) {
                uint32_t y = (mt[i] & 0x80000000u) | (mt[(i + 1) % 624] & 0x7fffffffu);
                mt[i] = mt[(i + 397) % 624] ^ (y >> 1) ^ ((y & 1u) ? 0x9908b0dfu : 0u);
            }
            mti = 0;
        }
        uint32_t y = mt[mti++];
        y ^= y >> 11;
        y ^= (y << 7) & 0x9d2c5680u;
        y ^= (y << 15) & 0xefc60000u;
        y ^= y >> 18;
        return y;
    }
    double rd() {
        uint32_t a = next() >> 5, b = next() >> 6;
        return (a * 67108864.0 + b) / 9007199254740992.0;
    }
    uint32_t masked(uint32_t rngmax, uint32_t mask) {
        for (;;) {
            uint32_t v = next() & mask;
            if (v <= rngmax) return v;
        }
    }
    double gauss() {
        if (has_gauss) { has_gauss = false; return gauss_cache; }
        double x1, x2, r2;
        do {
            x1 = 2.0 * rd() - 1.0;
            x2 = 2.0 * rd() - 1.0;
            r2 = x1 * x1 + x2 * x2;
        } while (r2 >= 1.0 || r2 == 0.0);
        double f = sqrt(-2.0 * log(r2) / r2);
        gauss_cache = f * x1;
        has_gauss = true;
        return f * x2;
    }
};

} // namespace mtrep

extern "C" void kernel_launch(void* const* d_in, const int* in_sizes, int n_in,
                              void* d_out, int out_size)
{
    (void)in_sizes; (void)n_in; (void)out_size;
    const float* sig = (const float*)d_in[0];
    const float* W   = (const float*)d_in[1];
    const float* B   = (const float*)d_in[2];
    float* out       = (float*)d_out;

    // ---- replicate gen_meta() ----
    static int kk[N_KERNELS], dd[N_KERNELS], pp[N_KERNELS];
    {
        mtrep::MT r;
        r.seed(0u);
        for (int i = 0; i < N_KERNELS; i++) {
            uint32_t c = r.masked(2u, 3u);               // choice of 3
            int k = (c == 0u) ? 7 : (c == 1u) ? 9 : 11;
            int emax = (k == 7) ? 12 : 11;               // int(log2((L-1)/(k-1)))
            uint32_t e = r.masked((uint32_t)(emax - 1), 15u);
            int d = 1 << e;
            double rv = r.rd();                          // rng.rand()
            int p = (rv <= 0.5) ? 0 : ((k - 1) * d / 2);
            (void)r.rd();                                // rng.uniform(-1,1) bias
            for (int q = 0; q < k; q++) (void)r.gauss(); // normal(size=k)
            kk[i] = k; dd[i] = d; pp[i] = p;
        }
    }

    // ---- group by (k,d,p), sort groups lexicographically (reference order) --
    static int gk[MAX_GROUPS], gd[MAX_GROUPS], gp[MAX_GROUPS], gcnt[MAX_GROUPS];
    static int gid_of[N_KERNELS];
    int ng = 0;
    for (int i = 0; i < N_KERNELS; i++) {
        int found = -1;
        for (int g = 0; g < ng; g++)
            if (gk[g] == kk[i] && gd[g] == dd[i] && gp[g] == pp[i]) { found = g; break; }
        if (found < 0) {
            found = ng++;
            gk[found] = kk[i]; gd[found] = dd[i]; gp[found] = pp[i]; gcnt[found] = 0;
        }
        gid_of[i] = found;
        gcnt[found]++;
    }
    static int order[MAX_GROUPS];
    for (int g = 0; g < ng; g++) order[g] = g;
    for (int a = 0; a < ng; a++) {                       // selection sort by (k,d,p)
        int best = a;
        for (int b = a + 1; b < ng; b++) {
            int ga_ = order[best], gb_ = order[b];
            bool lt = (gk[gb_] < gk[ga_]) ||
                      (gk[gb_] == gk[ga_] && (gd[gb_] < gd[ga_] ||
                       (gd[gb_] == gd[ga_] && gp[gb_] < gp[ga_])));
            if (lt) best = b;
        }
        int tmp = order[a]; order[a] = order[best]; order[best] = tmp;
    }

    // ---- build params in reference order (out offsets fixed by (k,d,p)) ----
    static Params prm;
    int pos = 0;
    long long off = 0;
    int tiles = 0, maxG = 1;
    for (int si = 0; si < ng; si++) {
        int g = order[si];
        int G = gcnt[g];
        int Lout = SIG_LEN + 2 * gp[g] - (gk[g] - 1) * gd[g];
        const int kcode = (gk[g] == 7) ? 0 : (gk[g] == 9) ? 1 : 2;
        const int mode = (gd[g] >= 4) ? 0 : 1;
        const int al = ((Lout & 3) == 0) ? 1 : 0;
        prm.gA[si] = make_int4(gd[g], gp[g], Lout, G);
        prm.gB[si] = make_int4(pos, (int)off, kcode * 4 + mode * 2 + al, 0);
        prm.tprefix[si] = tiles;
        tiles += (Lout + TILE - 1) / TILE;
        for (int i = 0; i < N_KERNELS; i++)
            if (gid_of[i] == g) prm.idx[pos++] = i;
        off += 2LL * G * Lout;
        if (G > maxG) maxG = G;
    }
    prm.tprefix[ng] = tiles;
    prm.ng = ng;

    // ---- single launch ----
    dim3 grid(tiles, 2);
    const int smem = WIN * (int)sizeof(float)
                   + maxG * (K_MAX + 1) * (int)sizeof(unsigned long long);
    rocket_all<<<grid, THREADS, smem>>>(prm, sig, W, B, out);
}